// round 3
// baseline (speedup 1.0000x reference)
#include <cuda_runtime.h>
#include <cstdint>

#define B_SZ   32
#define RESN   100
#define ITERS  1000
#define KSPLIT 16         // fc4 k-dim split (k-chunk = 32)
#define CSIZE  2          // cluster CTAs per sample
#define RPC    50         // rows per CTA
#define STRIDE 102        // padded SMEM row stride (words) — breaks mod-32 resonance

// -------- scratch (device globals; no allocation allowed) ----------
__device__ float g_h1[B_SZ * 128];
__device__ float g_h2[B_SZ * 256];
__device__ float g_h3[B_SZ * 512];
__device__ float g_part[KSPLIT * B_SZ * 10000];   // fc4 partial sums (20.5 MB)

// -------------------- MLP layers 1..3 (small) ----------------------
__global__ void fc1_kernel(const float* __restrict__ pores,
                           const float* __restrict__ W,
                           const float* __restrict__ bias) {
    int idx = blockIdx.x * blockDim.x + threadIdx.x;
    if (idx >= B_SZ * 128) return;
    int b = idx >> 7, j = idx & 127;
    float acc = bias[j];
#pragma unroll
    for (int k = 0; k < 25; k++)
        acc = fmaf(pores[b * 25 + k], W[k * 128 + j], acc);
    g_h1[idx] = fmaxf(acc, 0.0f);
}

__global__ void fc2_kernel(const float* __restrict__ W,
                           const float* __restrict__ bias) {
    int idx = blockIdx.x * blockDim.x + threadIdx.x;
    if (idx >= B_SZ * 256) return;
    int b = idx >> 8, j = idx & 255;
    float acc = bias[j];
#pragma unroll 8
    for (int k = 0; k < 128; k++)
        acc = fmaf(g_h1[b * 128 + k], W[k * 256 + j], acc);
    g_h2[idx] = fmaxf(acc, 0.0f);
}

__global__ void fc3_kernel(const float* __restrict__ W,
                           const float* __restrict__ bias) {
    int idx = blockIdx.x * blockDim.x + threadIdx.x;
    if (idx >= B_SZ * 512) return;
    int b = idx >> 9, j = idx & 511;
    float acc = bias[j];
#pragma unroll 8
    for (int k = 0; k < 256; k++)
        acc = fmaf(g_h2[b * 256 + k], W[k * 512 + j], acc);
    g_h3[idx] = fmaxf(acc, 0.0f);
}

// ---------------- fc4 stage 1: split-K partial sums ----------------
// grid (79, KSPLIT), block 128. Chunk of 32 k-values per block.
// Explicit unroll-by-4 on kk so 4 W-loads are in flight (MLP>=4).
__global__ __launch_bounds__(128) void fc4_partial_kernel(
    const float* __restrict__ W)     // [512,10000]
{
    __shared__ float h3s[B_SZ * 32];   // 4 KB h3 chunk
    int k0 = blockIdx.y * 32;
    for (int i = threadIdx.x; i < B_SZ * 32; i += blockDim.x) {
        int q = i >> 5, kk = i & 31;
        h3s[i] = g_h3[q * 512 + k0 + kk];
    }
    __syncthreads();

    int o = blockIdx.x * blockDim.x + threadIdx.x;
    if (o >= RESN * RESN) return;

    float acc[B_SZ];
#pragma unroll
    for (int q = 0; q < B_SZ; q++) acc[q] = 0.0f;

#pragma unroll
    for (int kk = 0; kk < 32; kk += 4) {
        float w0 = W[(k0 + kk + 0) * 10000 + o];
        float w1 = W[(k0 + kk + 1) * 10000 + o];
        float w2 = W[(k0 + kk + 2) * 10000 + o];
        float w3 = W[(k0 + kk + 3) * 10000 + o];
#pragma unroll
        for (int q = 0; q < B_SZ; q++) {
            acc[q] = fmaf(h3s[q * 32 + kk + 0], w0, acc[q]);
            acc[q] = fmaf(h3s[q * 32 + kk + 1], w1, acc[q]);
            acc[q] = fmaf(h3s[q * 32 + kk + 2], w2, acc[q]);
            acc[q] = fmaf(h3s[q * 32 + kk + 3], w3, acc[q]);
        }
    }

    float* dst = g_part + blockIdx.y * (B_SZ * 10000);
#pragma unroll
    for (int q = 0; q < B_SZ; q++)
        dst[q * 10000 + o] = acc[q];
}

// -------- fc4 stage 2: reduce + bias + residual + clamp ------------
__global__ __launch_bounds__(128) void fc4_final_kernel(
    const float* __restrict__ bias,  // [10000]
    const float* __restrict__ pores, // [32,25]
    float* __restrict__ cond)        // [32,10000]
{
    int o = blockIdx.x * blockDim.x + threadIdx.x;
    if (o >= RESN * RESN) return;
    int i = o / RESN, j = o % RESN;
    int pidx = (i / 20) * 5 + (j / 20);
    float bb = bias[o];
#pragma unroll 4
    for (int q = 0; q < B_SZ; q++) {
        float s = bb;
#pragma unroll
        for (int p = 0; p < KSPLIT; p++)
            s += g_part[p * (B_SZ * 10000) + q * 10000 + o];
        float base = 1.0f - pores[q * 25 + pidx];
        cond[q * 10000 + o] = fmaxf(s + base, 0.01f);
    }
}

// ----------------- cluster mbarrier / DSMEM helpers ----------------
__device__ __forceinline__ uint32_t smem_u32(const void* p) {
    uint32_t a;
    asm("{ .reg .u64 t; cvta.to.shared.u64 t, %1; cvt.u32.u64 %0, t; }"
        : "=r"(a) : "l"(p));
    return a;
}

__device__ __forceinline__ void mbar_init(uint32_t mbar, uint32_t count) {
    asm volatile("mbarrier.init.shared.b64 [%0], %1;" :: "r"(mbar), "r"(count) : "memory");
}

__device__ __forceinline__ void mbar_wait_cluster(uint32_t mbar, uint32_t parity) {
    asm volatile(
        "{\n\t.reg .pred P;\n\t"
        "WL_%=:\n\t"
        "mbarrier.try_wait.parity.acquire.cluster.shared::cta.b64 P, [%0], %1, 0x989680;\n\t"
        "@P bra.uni WD_%=;\n\t"
        "bra.uni WL_%=;\n\t"
        "WD_%=:\n\t}"
        :: "r"(mbar), "r"(parity) : "memory");
}

__device__ __forceinline__ void mbar_arrive_peer(uint32_t local_mbar, uint32_t rank) {
    asm volatile(
        "{\n\t.reg .b32 ra;\n\t"
        "mapa.shared::cluster.u32 ra, %0, %1;\n\t"
        "mbarrier.arrive.release.cluster.shared::cluster.b64 _, [ra];\n\t}"
        :: "r"(local_mbar), "r"(rank) : "memory");
}

__device__ __forceinline__ void dsmem_st_v2(uint32_t local_addr, uint32_t rank, float2 v) {
    asm volatile(
        "{\n\t.reg .b32 ra;\n\t"
        "mapa.shared::cluster.u32 ra, %0, %1;\n\t"
        "st.shared::cluster.v2.f32 [ra], {%2, %3};\n\t}"
        :: "r"(local_addr), "r"(rank), "f"(v.x), "f"(v.y)
        : "memory");
}

// ------------------- Jacobi: 2-CTA cluster per sample ---------------
// grid = 64 (32 samples x 2 cluster CTAs), 512 threads (500 active).
// Thread (r = tid/10 in [0,50), s = tid%10) owns a 10-col row segment.
// SMEM field double-buffered, 52 rows x STRIDE: row 0 = top halo,
// rows 1..50 = own, row 51 = bottom halo. Edge rows PUSHED into the
// neighbor's halo of the next buffer via st.shared::cluster, signaled
// with pairwise mbarriers (10 arrivals = 10 segment threads).
__global__ __launch_bounds__(512, 1) __cluster_dims__(CSIZE, 1, 1)
void jacobi_kernel(const float* __restrict__ cond,   // [32,10000]
                   float* __restrict__ kappa)        // [32]
{
    __shared__ float Tbuf[2][52 * STRIDE];
    __shared__ float partial[10];
    __shared__ uint64_t mbar_up_s, mbar_dn_s;

    int tid  = threadIdx.x;
    int rank = blockIdx.x & 1;
    int b    = blockIdx.x >> 1;
    const float* k = cond + b * 10000;

    bool act = tid < 500;
    int r  = tid / 10;           // local row 0..49
    int s  = tid % 10;
    int c0 = s * 10;
    int rg = rank * RPC + r;     // global row

    uint32_t mbar_up = smem_u32(&mbar_up_s);   // my TOP halo filled
    uint32_t mbar_dn = smem_u32(&mbar_dn_s);   // my BOTTOM halo filled
    if (tid == 0) { mbar_init(mbar_up, 10); mbar_init(mbar_dn, 10); }

    bool top_edge = act && (r == 0)  && (rank == 1);  // waits mbar_up; pushes row up
    bool bot_edge = act && (r == 49) && (rank == 0);  // waits mbar_dn; pushes row down

    // ---- per-thread coefficients (registers) ----
    float rN[10], rS[10], rW[10], rE[10], Tc[10];
    if (act) {
        int rm = (rg == 0)  ? 0  : rg - 1;
        int rp = (rg == 99) ? 99 : rg + 1;
#pragma unroll
        for (int j = 0; j < 10; j++) {
            int c  = c0 + j;
            int cm = (c == 0)  ? 0  : c - 1;
            int cp = (c == 99) ? 99 : c + 1;
            float kc = k[rg * 100 + c];
            float kn = 0.5f * (kc + k[rm * 100 + c]);
            float ks = 0.5f * (kc + k[rp * 100 + c]);
            float kw = 0.5f * (kc + k[rg * 100 + cm]);
            float ke = 0.5f * (kc + k[rg * 100 + cp]);
            float inv = 1.0f / (kn + ks + kw + ke + 1e-12f);
            rN[j] = kn * inv; rS[j] = ks * inv;
            rW[j] = kw * inv; rE[j] = ke * inv;
        }
        float tv = 1.0f - (float)rg * (1.0f / 99.0f);
#pragma unroll
        for (int j = 0; j < 10; j++) {
            Tc[j] = tv;
            Tbuf[0][(r + 1) * STRIDE + c0 + j] = tv;
        }
    }
    // initial halos of buffer 0 (iteration-0 input field is analytic)
    if (tid < 100) {
        if (rank == 1)   // top halo = global row 49
            Tbuf[0][0 * STRIDE + tid]  = 1.0f - 49.0f * (1.0f / 99.0f);
        else             // bottom halo = global row 50
            Tbuf[0][51 * STRIDE + tid] = 1.0f - 50.0f * (1.0f / 99.0f);
    }
    __syncthreads();
    asm volatile("barrier.cluster.arrive.aligned;" ::: "memory");
    asm volatile("barrier.cluster.wait.aligned;"   ::: "memory");

    int cur = 0;
    for (int it = 0; it < ITERS; ++it) {
        int nxt = cur ^ 1;
        if (act) {
            if (it > 0) {
                int wp = (it - 1) & 1;
                if (top_edge) mbar_wait_cluster(mbar_up, wp);
                if (bot_edge) mbar_wait_cluster(mbar_dn, wp);
            }
            float* C  = Tbuf[cur];
            float* Nx = Tbuf[nxt];
            int base = (r + 1) * STRIDE + c0;

            float left   = (s == 0) ? Tc[0] : C[base - 1];
            float rightb = (s == 9) ? Tc[9] : C[base + 10];
            const float2* nrow = reinterpret_cast<const float2*>(C + base - STRIDE);
            const float2* srow = reinterpret_cast<const float2*>(C + base + STRIDE);
            float2* orow = reinterpret_cast<float2*>(Nx + base);

            float prev = left;
            float2 outv[5];
#pragma unroll
            for (int m = 0; m < 5; m++) {
                float2 n2 = (rg == 0)  ? make_float2(1.f, 1.f) : nrow[m];
                float2 s2 = (rg == 99) ? make_float2(0.f, 0.f) : srow[m];
                float tn[2] = {n2.x, n2.y};
                float ts[2] = {s2.x, s2.y};
                float res[2];
#pragma unroll
                for (int jj = 0; jj < 2; jj++) {
                    int j = 2 * m + jj;
                    float right = (j == 9) ? rightb : Tc[j + 1];
                    float old = Tc[j];
                    float v = fmaf(rN[j], tn[jj],
                              fmaf(rS[j], ts[jj],
                              fmaf(rW[j], prev, rE[j] * right)));
                    Tc[j] = v;
                    res[jj] = v;
                    prev = old;
                }
                outv[m] = make_float2(res[0], res[1]);
                orow[m] = outv[m];
            }

            // push new edge row into the peer's halo of THEIR nxt buffer
            if (top_edge) {   // rank1 row0 (global 50) -> rank0 bottom halo (row 51)
                uint32_t dst = smem_u32(&Tbuf[nxt][51 * STRIDE + c0]);
#pragma unroll
                for (int m = 0; m < 5; m++)
                    dsmem_st_v2(dst + m * 8, 0, outv[m]);
                mbar_arrive_peer(mbar_dn, 0);
            }
            if (bot_edge) {   // rank0 row49 (global 49) -> rank1 top halo (row 0)
                uint32_t dst = smem_u32(&Tbuf[nxt][0 * STRIDE + c0]);
#pragma unroll
                for (int m = 0; m < 5; m++)
                    dsmem_st_v2(dst + m * 8, 1, outv[m]);
                mbar_arrive_peer(mbar_up, 1);
            }
        }
        __syncthreads();
        cur ^= 1;
    }

    // kappa from global top row (rank 0 only)
    if (rank == 0) {
        if (act && r == 0) {
            float p = 0.0f;
#pragma unroll
            for (int j = 0; j < 10; j++)
                p += k[c0 + j] * (1.0f - Tc[j]);
            partial[s] = p;
        }
        __syncthreads();
        if (tid == 0) {
            float sum = 0.0f;
#pragma unroll
            for (int q = 0; q < 10; q++) sum += partial[q];
            kappa[b] = 2.0f * sum;
        }
    }

    // no CTA may exit while a peer could still push into its SMEM
    asm volatile("barrier.cluster.arrive.aligned;" ::: "memory");
    asm volatile("barrier.cluster.wait.aligned;"   ::: "memory");
}

// --------------------------- launcher ------------------------------
extern "C" void kernel_launch(void* const* d_in, const int* in_sizes, int n_in,
                              void* d_out, int out_size) {
    const float* pores = (const float*)d_in[0];
    const float* W1 = (const float*)d_in[1];
    const float* b1 = (const float*)d_in[2];
    const float* W2 = (const float*)d_in[3];
    const float* b2 = (const float*)d_in[4];
    const float* W3 = (const float*)d_in[5];
    const float* b3 = (const float*)d_in[6];
    const float* W4 = (const float*)d_in[7];
    const float* b4 = (const float*)d_in[8];

    float* out   = (float*)d_out;
    float* kappa = out;          // [32]
    float* cond  = out + B_SZ;   // [32,100,100]

    fc1_kernel<<<(B_SZ * 128 + 255) / 256, 256>>>(pores, W1, b1);
    fc2_kernel<<<(B_SZ * 256 + 255) / 256, 256>>>(W2, b2);
    fc3_kernel<<<(B_SZ * 512 + 255) / 256, 256>>>(W3, b3);
    dim3 g4((10000 + 127) / 128, KSPLIT);
    fc4_partial_kernel<<<g4, 128>>>(W4);
    fc4_final_kernel<<<(10000 + 127) / 128, 128>>>(b4, pores, cond);
    jacobi_kernel<<<B_SZ * CSIZE, 512>>>(cond, kappa);
}

// round 4
// speedup vs baseline: 1.1860x; 1.1860x over previous
#include <cuda_runtime.h>
#include <cstdint>

#define B_SZ   32
#define RESN   100
#define ITERS  1000
#define KSPLIT 16         // fc4 k-dim split (k-chunk = 32)

// Jacobi tiling: 500 threads, each owns h=5 rows x w=4 cols in registers.
#define TBANDS 20         // tile rows of 5
#define TCOLS  25         // tile cols of 4
#define TH     5
#define TW     4
#define CSTR   101        // column-array stride (conflict-free: 5*t mod 32 cycles)
#define BUFW   9056       // words per edge buffer (16B-aligned)

// -------- scratch (device globals; no allocation allowed) ----------
__device__ float g_h1[B_SZ * 128];
__device__ float g_h2[B_SZ * 256];
__device__ float g_h3[B_SZ * 512];
__device__ float g_part[KSPLIT * B_SZ * 10000];   // fc4 partial sums

// -------------------- MLP layers 1..3 (small) ----------------------
__global__ void fc1_kernel(const float* __restrict__ pores,
                           const float* __restrict__ W,
                           const float* __restrict__ bias) {
    int idx = blockIdx.x * blockDim.x + threadIdx.x;
    if (idx >= B_SZ * 128) return;
    int b = idx >> 7, j = idx & 127;
    float acc = bias[j];
#pragma unroll
    for (int k = 0; k < 25; k++)
        acc = fmaf(pores[b * 25 + k], W[k * 128 + j], acc);
    g_h1[idx] = fmaxf(acc, 0.0f);
}

__global__ void fc2_kernel(const float* __restrict__ W,
                           const float* __restrict__ bias) {
    int idx = blockIdx.x * blockDim.x + threadIdx.x;
    if (idx >= B_SZ * 256) return;
    int b = idx >> 8, j = idx & 255;
    float acc = bias[j];
#pragma unroll 8
    for (int k = 0; k < 128; k++)
        acc = fmaf(g_h1[b * 128 + k], W[k * 256 + j], acc);
    g_h2[idx] = fmaxf(acc, 0.0f);
}

__global__ void fc3_kernel(const float* __restrict__ W,
                           const float* __restrict__ bias) {
    int idx = blockIdx.x * blockDim.x + threadIdx.x;
    if (idx >= B_SZ * 512) return;
    int b = idx >> 9, j = idx & 511;
    float acc = bias[j];
#pragma unroll 8
    for (int k = 0; k < 256; k++)
        acc = fmaf(g_h2[b * 256 + k], W[k * 512 + j], acc);
    g_h3[idx] = fmaxf(acc, 0.0f);
}

// ---------------- fc4 stage 1: split-K partial sums ----------------
__global__ __launch_bounds__(128) void fc4_partial_kernel(
    const float* __restrict__ W)     // [512,10000]
{
    __shared__ float h3s[B_SZ * 32];
    int k0 = blockIdx.y * 32;
    for (int i = threadIdx.x; i < B_SZ * 32; i += blockDim.x) {
        int q = i >> 5, kk = i & 31;
        h3s[i] = g_h3[q * 512 + k0 + kk];
    }
    __syncthreads();

    int o = blockIdx.x * blockDim.x + threadIdx.x;
    if (o >= RESN * RESN) return;

    float acc[B_SZ];
#pragma unroll
    for (int q = 0; q < B_SZ; q++) acc[q] = 0.0f;

#pragma unroll
    for (int kk = 0; kk < 32; kk += 4) {
        float w0 = W[(k0 + kk + 0) * 10000 + o];
        float w1 = W[(k0 + kk + 1) * 10000 + o];
        float w2 = W[(k0 + kk + 2) * 10000 + o];
        float w3 = W[(k0 + kk + 3) * 10000 + o];
#pragma unroll
        for (int q = 0; q < B_SZ; q++) {
            acc[q] = fmaf(h3s[q * 32 + kk + 0], w0, acc[q]);
            acc[q] = fmaf(h3s[q * 32 + kk + 1], w1, acc[q]);
            acc[q] = fmaf(h3s[q * 32 + kk + 2], w2, acc[q]);
            acc[q] = fmaf(h3s[q * 32 + kk + 3], w3, acc[q]);
        }
    }

    float* dst = g_part + blockIdx.y * (B_SZ * 10000);
#pragma unroll
    for (int q = 0; q < B_SZ; q++)
        dst[q * 10000 + o] = acc[q];
}

// -------- fc4 stage 2: reduce + bias + residual + clamp ------------
// grid (79, 8): blockIdx.y covers 4 batch samples -> 632 blocks.
__global__ __launch_bounds__(128) void fc4_final_kernel(
    const float* __restrict__ bias,  // [10000]
    const float* __restrict__ pores, // [32,25]
    float* __restrict__ cond)        // [32,10000]
{
    int o = blockIdx.x * blockDim.x + threadIdx.x;
    if (o >= RESN * RESN) return;
    int i = o / RESN, j = o % RESN;
    int pidx = (i / 20) * 5 + (j / 20);
    float bb = bias[o];
    int q0 = blockIdx.y * 4;
#pragma unroll
    for (int qq = 0; qq < 4; qq++) {
        int q = q0 + qq;
        float s = bb;
#pragma unroll
        for (int p = 0; p < KSPLIT; p++)
            s += g_part[p * (B_SZ * 10000) + q * 10000 + o];
        float base = 1.0f - pores[q * 25 + pidx];
        cond[q * 10000 + o] = fmaxf(s + base, 0.01f);
    }
}

// ------------------- Jacobi: register-tiled, 1 CTA/sample ---------------
// 512 threads (500 active). Thread (band = tid/25 in [0,20), tcol = tid%25)
// owns rows [5*band, 5*band+5) x cols [4*tcol, 4*tcol+4) in REGISTERS.
// Only tile-perimeter values go through SMEM (double-buffered):
//   Rtop[band][100]  : top    row of each 5-row band   (float4 access)
//   Rbot[band][100]  : bottom row of each band
//   Cleft[tcol][101] : left  col of each 4-col strip   (scalar, stride 101)
//   Cright[tcol][101]: right col of each strip
__global__ __launch_bounds__(512, 1)
void jacobi_kernel(const float* __restrict__ cond,   // [32,10000]
                   float* __restrict__ kappa)        // [32]
{
    extern __shared__ float sm[];
    // buffer layout (words): rtop 0..2000, rbot 2000..4000,
    //                        cleft 4000..6525, cright 6525..9050
    float* partial = sm + 2 * BUFW;   // 25 floats

    int b = blockIdx.x;
    const float* k = cond + b * 10000;
    int tid = threadIdx.x;
    bool act = tid < 500;
    int band = tid / 25;          // 0..19
    int tcol = tid % 25;          // 0..24
    int r0 = band * TH;
    int c0 = tcol * TW;

    float rN[TH][TW], rS[TH][TW], rW[TH][TW], rE[TH][TW], Tc[TH][TW];

    if (act) {
#pragma unroll
        for (int i = 0; i < TH; i++) {
            int rg = r0 + i;
            int rm = (rg == 0)  ? 0  : rg - 1;
            int rp = (rg == 99) ? 99 : rg + 1;
#pragma unroll
            for (int j = 0; j < TW; j++) {
                int c  = c0 + j;
                int cm = (c == 0)  ? 0  : c - 1;
                int cp = (c == 99) ? 99 : c + 1;
                float kc = k[rg * 100 + c];
                float kn = 0.5f * (kc + k[rm * 100 + c]);
                float ks = 0.5f * (kc + k[rp * 100 + c]);
                float kw = 0.5f * (kc + k[rg * 100 + cm]);
                float ke = 0.5f * (kc + k[rg * 100 + cp]);
                float inv = 1.0f / (kn + ks + kw + ke + 1e-12f);
                rN[i][j] = kn * inv; rS[i][j] = ks * inv;
                rW[i][j] = kw * inv; rE[i][j] = ke * inv;
            }
        }
        // initial field + initial OLD edge buffers (buffer 0)
        float* rtop0 = sm;
        float* rbot0 = sm + 2000;
        float* clft0 = sm + 4000;
        float* crgt0 = sm + 6525;
#pragma unroll
        for (int i = 0; i < TH; i++) {
            float tv = 1.0f - (float)(r0 + i) * (1.0f / 99.0f);
#pragma unroll
            for (int j = 0; j < TW; j++) Tc[i][j] = tv;
            clft0[tcol * CSTR + r0 + i] = tv;
            crgt0[tcol * CSTR + r0 + i] = tv;
        }
        {
            float tvt = 1.0f - (float)r0 * (1.0f / 99.0f);
            float tvb = 1.0f - (float)(r0 + TH - 1) * (1.0f / 99.0f);
#pragma unroll
            for (int j = 0; j < TW; j++) {
                rtop0[band * 100 + c0 + j] = tvt;
                rbot0[band * 100 + c0 + j] = tvb;
            }
        }
    }
    __syncthreads();

    int cur = 0;
    for (int it = 0; it < ITERS; ++it) {
        if (act) {
            float* bufC = sm + cur * BUFW;
            float* bufN = sm + (cur ^ 1) * BUFW;
            const float* rtopO = bufC;          // old tops
            const float* rbotO = bufC + 2000;   // old bottoms
            const float* clftO = bufC + 4000;
            const float* crgtO = bufC + 6525;
            float* rtopW = bufN;
            float* rbotW = bufN + 2000;
            float* clftW = bufN + 4000;
            float* crgtW = bufN + 6525;

            // ---- halo reads (OLD values) ----
            float4 north = (band == 0)
                ? make_float4(1.f, 1.f, 1.f, 1.f)
                : *reinterpret_cast<const float4*>(rbotO + (band - 1) * 100 + c0);
            float4 south = (band == TBANDS - 1)
                ? make_float4(0.f, 0.f, 0.f, 0.f)
                : *reinterpret_cast<const float4*>(rtopO + (band + 1) * 100 + c0);

            // rolling in-place Jacobi over the 5-row tile
            float po[TW] = {north.x, north.y, north.z, north.w};
#pragma unroll
            for (int i = 0; i < TH; i++) {
                float old0 = Tc[i][0], old1 = Tc[i][1], old2 = Tc[i][2], old3 = Tc[i][3];
                float so0, so1, so2, so3;
                if (i < TH - 1) { so0 = Tc[i+1][0]; so1 = Tc[i+1][1]; so2 = Tc[i+1][2]; so3 = Tc[i+1][3]; }
                else            { so0 = south.x;    so1 = south.y;    so2 = south.z;    so3 = south.w; }
                float wv = (tcol == 0)  ? old0 : crgtO[(tcol - 1) * CSTR + r0 + i];
                float ev = (tcol == 24) ? old3 : clftO[(tcol + 1) * CSTR + r0 + i];

                Tc[i][0] = fmaf(rN[i][0], po[0], fmaf(rS[i][0], so0,
                           fmaf(rW[i][0], wv,   rE[i][0] * old1)));
                Tc[i][1] = fmaf(rN[i][1], po[1], fmaf(rS[i][1], so1,
                           fmaf(rW[i][1], old0, rE[i][1] * old2)));
                Tc[i][2] = fmaf(rN[i][2], po[2], fmaf(rS[i][2], so2,
                           fmaf(rW[i][2], old1, rE[i][2] * old3)));
                Tc[i][3] = fmaf(rN[i][3], po[3], fmaf(rS[i][3], so3,
                           fmaf(rW[i][3], old2, rE[i][3] * ev)));

                po[0] = old0; po[1] = old1; po[2] = old2; po[3] = old3;

                // publish left/right edges of NEW row i
                clftW[tcol * CSTR + r0 + i] = Tc[i][0];
                crgtW[tcol * CSTR + r0 + i] = Tc[i][3];
            }
            // publish new top/bottom rows of the band
            *reinterpret_cast<float4*>(rtopW + band * 100 + c0) =
                make_float4(Tc[0][0], Tc[0][1], Tc[0][2], Tc[0][3]);
            *reinterpret_cast<float4*>(rbotW + band * 100 + c0) =
                make_float4(Tc[TH-1][0], Tc[TH-1][1], Tc[TH-1][2], Tc[TH-1][3]);
        }
        __syncthreads();
        cur ^= 1;
    }

    // kappa = 2 * sum_c k[0,c] * (1 - T[0,c])   (top-band threads hold row 0)
    if (act && band == 0) {
        float p = 0.0f;
#pragma unroll
        for (int j = 0; j < TW; j++)
            p += k[c0 + j] * (1.0f - Tc[0][j]);
        partial[tcol] = p;
    }
    __syncthreads();
    if (tid == 0) {
        float sum = 0.0f;
#pragma unroll
        for (int q = 0; q < 25; q++) sum += partial[q];
        kappa[b] = 2.0f * sum;
    }
}

// --------------------------- launcher ------------------------------
extern "C" void kernel_launch(void* const* d_in, const int* in_sizes, int n_in,
                              void* d_out, int out_size) {
    const float* pores = (const float*)d_in[0];
    const float* W1 = (const float*)d_in[1];
    const float* b1 = (const float*)d_in[2];
    const float* W2 = (const float*)d_in[3];
    const float* b2 = (const float*)d_in[4];
    const float* W3 = (const float*)d_in[5];
    const float* b3 = (const float*)d_in[6];
    const float* W4 = (const float*)d_in[7];
    const float* b4 = (const float*)d_in[8];

    float* out   = (float*)d_out;
    float* kappa = out;          // [32]
    float* cond  = out + B_SZ;   // [32,100,100]

    const int SMEM_JAC = (2 * BUFW + 32) * sizeof(float);  // ~72.6 KB
    cudaFuncSetAttribute(jacobi_kernel, cudaFuncAttributeMaxDynamicSharedMemorySize, SMEM_JAC);

    fc1_kernel<<<(B_SZ * 128 + 255) / 256, 256>>>(pores, W1, b1);
    fc2_kernel<<<(B_SZ * 256 + 255) / 256, 256>>>(W2, b2);
    fc3_kernel<<<(B_SZ * 512 + 255) / 256, 256>>>(W3, b3);
    dim3 g4((10000 + 127) / 128, KSPLIT);
    fc4_partial_kernel<<<g4, 128>>>(W4);
    dim3 g5((10000 + 127) / 128, B_SZ / 4);
    fc4_final_kernel<<<g5, 128>>>(b4, pores, cond);
    jacobi_kernel<<<B_SZ, 512, SMEM_JAC>>>(cond, kappa);
}

// round 5
// speedup vs baseline: 1.4621x; 1.2328x over previous
#include <cuda_runtime.h>
#include <cstdint>

#define B_SZ   32
#define RESN   100
#define ITERS  1000
#define KSPLIT 16         // fc4 k-dim split (k-chunk = 32)

typedef unsigned long long ull;

// -------- scratch (device globals; no allocation allowed) ----------
__device__ float g_h1[B_SZ * 128];
__device__ float g_h2[B_SZ * 256];
__device__ float g_h3[B_SZ * 512];
__device__ float g_part[KSPLIT * B_SZ * 10000];   // fc4 partial sums

// ---------------------- f32x2 helpers (FFMA2) ----------------------
__device__ __forceinline__ ull pack2(float lo, float hi) {
    ull r; unsigned a = __float_as_uint(lo), b = __float_as_uint(hi);
    asm("mov.b64 %0, {%1,%2};" : "=l"(r) : "r"(a), "r"(b));
    return r;
}
__device__ __forceinline__ float lo2(ull v) {
    unsigned a, b;
    asm("mov.b64 {%0,%1}, %2;" : "=r"(a), "=r"(b) : "l"(v));
    return __uint_as_float(a);
}
__device__ __forceinline__ float hi2(ull v) {
    unsigned a, b;
    asm("mov.b64 {%0,%1}, %2;" : "=r"(a), "=r"(b) : "l"(v));
    return __uint_as_float(b);
}
// (hi(a), lo(b)) — the "shifted" pair for W/E stencil operands
__device__ __forceinline__ ull shift_pair(ull a, ull b) {
    unsigned a0, a1, b0, b1;
    asm("mov.b64 {%0,%1}, %2;" : "=r"(a0), "=r"(a1) : "l"(a));
    asm("mov.b64 {%0,%1}, %2;" : "=r"(b0), "=r"(b1) : "l"(b));
    ull r;
    asm("mov.b64 %0, {%1,%2};" : "=l"(r) : "r"(a1), "r"(b0));
    return r;
}
__device__ __forceinline__ ull fma2(ull a, ull b, ull c) {
    ull d;
    asm("fma.rn.f32x2 %0, %1, %2, %3;" : "=l"(d) : "l"(a), "l"(b), "l"(c));
    return d;
}
__device__ __forceinline__ ull mul2(ull a, ull b) {
    ull d;
    asm("mul.rn.f32x2 %0, %1, %2;" : "=l"(d) : "l"(a), "l"(b));
    return d;
}

// -------------------- MLP layers 1..3 (small) ----------------------
__global__ void fc1_kernel(const float* __restrict__ pores,
                           const float* __restrict__ W,
                           const float* __restrict__ bias) {
    int idx = blockIdx.x * blockDim.x + threadIdx.x;
    if (idx >= B_SZ * 128) return;
    int b = idx >> 7, j = idx & 127;
    float acc = bias[j];
#pragma unroll
    for (int k = 0; k < 25; k++)
        acc = fmaf(pores[b * 25 + k], W[k * 128 + j], acc);
    g_h1[idx] = fmaxf(acc, 0.0f);
}

__global__ void fc2_kernel(const float* __restrict__ W,
                           const float* __restrict__ bias) {
    int idx = blockIdx.x * blockDim.x + threadIdx.x;
    if (idx >= B_SZ * 256) return;
    int b = idx >> 8, j = idx & 255;
    float acc = bias[j];
#pragma unroll 8
    for (int k = 0; k < 128; k++)
        acc = fmaf(g_h1[b * 128 + k], W[k * 256 + j], acc);
    g_h2[idx] = fmaxf(acc, 0.0f);
}

__global__ void fc3_kernel(const float* __restrict__ W,
                           const float* __restrict__ bias) {
    int idx = blockIdx.x * blockDim.x + threadIdx.x;
    if (idx >= B_SZ * 512) return;
    int b = idx >> 9, j = idx & 511;
    float acc = bias[j];
#pragma unroll 8
    for (int k = 0; k < 256; k++)
        acc = fmaf(g_h2[b * 256 + k], W[k * 512 + j], acc);
    g_h3[idx] = fmaxf(acc, 0.0f);
}

// ---------------- fc4 stage 1: split-K partial sums ----------------
__global__ __launch_bounds__(128) void fc4_partial_kernel(
    const float* __restrict__ W)     // [512,10000]
{
    __shared__ float h3s[B_SZ * 32];
    int k0 = blockIdx.y * 32;
    for (int i = threadIdx.x; i < B_SZ * 32; i += blockDim.x) {
        int q = i >> 5, kk = i & 31;
        h3s[i] = g_h3[q * 512 + k0 + kk];
    }
    __syncthreads();

    int o = blockIdx.x * blockDim.x + threadIdx.x;
    if (o >= RESN * RESN) return;

    float acc[B_SZ];
#pragma unroll
    for (int q = 0; q < B_SZ; q++) acc[q] = 0.0f;

#pragma unroll
    for (int kk = 0; kk < 32; kk += 4) {
        float w0 = W[(k0 + kk + 0) * 10000 + o];
        float w1 = W[(k0 + kk + 1) * 10000 + o];
        float w2 = W[(k0 + kk + 2) * 10000 + o];
        float w3 = W[(k0 + kk + 3) * 10000 + o];
#pragma unroll
        for (int q = 0; q < B_SZ; q++) {
            acc[q] = fmaf(h3s[q * 32 + kk + 0], w0, acc[q]);
            acc[q] = fmaf(h3s[q * 32 + kk + 1], w1, acc[q]);
            acc[q] = fmaf(h3s[q * 32 + kk + 2], w2, acc[q]);
            acc[q] = fmaf(h3s[q * 32 + kk + 3], w3, acc[q]);
        }
    }

    float* dst = g_part + blockIdx.y * (B_SZ * 10000);
#pragma unroll
    for (int q = 0; q < B_SZ; q++)
        dst[q * 10000 + o] = acc[q];
}

// -------- fc4 stage 2: reduce + bias + residual + clamp ------------
__global__ __launch_bounds__(128) void fc4_final_kernel(
    const float* __restrict__ bias,  // [10000]
    const float* __restrict__ pores, // [32,25]
    float* __restrict__ cond)        // [32,10000]
{
    int o = blockIdx.x * blockDim.x + threadIdx.x;
    if (o >= RESN * RESN) return;
    int i = o / RESN, j = o % RESN;
    int pidx = (i / 20) * 5 + (j / 20);
    float bb = bias[o];
    int q0 = blockIdx.y * 4;
#pragma unroll
    for (int qq = 0; qq < 4; qq++) {
        int q = q0 + qq;
        float s = bb;
#pragma unroll
        for (int p = 0; p < KSPLIT; p++)
            s += g_part[p * (B_SZ * 10000) + q * 10000 + o];
        float base = 1.0f - pores[q * 25 + pidx];
        cond[q * 10000 + o] = fmaxf(s + base, 0.01f);
    }
}

// ------------- Jacobi: R1 layout + packed f32x2 math ----------------
// One CTA per sample, 512 threads (500 active). Thread (r = tid%100,
// s = tid/100) owns row r, cols [20s, 20s+20) as 10 packed f32x2 pairs.
// T double-buffered in SMEM; N/S rows loaded as ulonglong2 (2 pairs per
// 16B). Stencil via fma.rn.f32x2: 40 FFMA2 instead of 80 FFMA per iter.
__global__ __launch_bounds__(512, 1)
void jacobi_kernel(const float* __restrict__ cond,   // [32,10000]
                   float* __restrict__ kappa)        // [32]
{
    extern __shared__ float sm[];
    float* Ta = sm;               // 10000
    float* Tb = sm + 10000;       // 10000
    float* partial = sm + 20000;  // 5

    int b = blockIdx.x;
    const float* k = cond + b * 10000;
    int tid = threadIdx.x;
    bool act = tid < 500;
    int r  = tid % 100;
    int s  = tid / 100;
    int c0 = s * 20;

    const ull ONE2  = 0x3F8000003F800000ULL;   // (1.0f, 1.0f)
    const ull ZERO2 = 0ULL;

    ull cN[10], cS[10], cW[10], cE[10], P[10];

    if (act) {
        int rm = (r == 0)  ? 0  : r - 1;
        int rp = (r == 99) ? 99 : r + 1;
        float fN[20], fS[20], fW[20], fE[20];
#pragma unroll
        for (int j = 0; j < 20; j++) {
            int c  = c0 + j;
            int cm = (c == 0)  ? 0  : c - 1;
            int cp = (c == 99) ? 99 : c + 1;
            float kc = k[r * 100 + c];
            float kn = 0.5f * (kc + k[rm * 100 + c]);
            float ks = 0.5f * (kc + k[rp * 100 + c]);
            float kw = 0.5f * (kc + k[r * 100 + cm]);
            float ke = 0.5f * (kc + k[r * 100 + cp]);
            float inv = 1.0f / (kn + ks + kw + ke + 1e-12f);
            fN[j] = kn * inv; fS[j] = ks * inv;
            fW[j] = kw * inv; fE[j] = ke * inv;
        }
#pragma unroll
        for (int m = 0; m < 10; m++) {
            cN[m] = pack2(fN[2*m], fN[2*m+1]);
            cS[m] = pack2(fS[2*m], fS[2*m+1]);
            cW[m] = pack2(fW[2*m], fW[2*m+1]);
            cE[m] = pack2(fE[2*m], fE[2*m+1]);
        }
        float tv = 1.0f - (float)r * (1.0f / 99.0f);
        ull tv2 = pack2(tv, tv);
#pragma unroll
        for (int m = 0; m < 10; m++) P[m] = tv2;
        ulonglong2* irow = reinterpret_cast<ulonglong2*>(Ta + r * 100 + c0);
#pragma unroll
        for (int mm = 0; mm < 5; mm++) {
            ulonglong2 v; v.x = tv2; v.y = tv2;
            irow[mm] = v;
        }
    }
    __syncthreads();

    float* cur = Ta;
    float* nxt = Tb;

    for (int it = 0; it < ITERS; ++it) {
        if (act) {
            int base = r * 100 + c0;
            float left   = (s == 0) ? lo2(P[0]) : cur[base - 1];
            float rightb = (s == 4) ? hi2(P[9]) : cur[base + 20];
            // clamped addresses: boundary rows read own row, value overridden
            const ulonglong2* nrow = reinterpret_cast<const ulonglong2*>(
                cur + ((r == 0)  ? base : base - 100));
            const ulonglong2* srow = reinterpret_cast<const ulonglong2*>(
                cur + ((r == 99) ? base : base + 100));
            ulonglong2* orow = reinterpret_cast<ulonglong2*>(nxt + base);

            ull Scur = pack2(left, lo2(P[0]));   // S_0
#pragma unroll
            for (int mm = 0; mm < 5; mm++) {
                ulonglong2 nv = nrow[mm];
                ulonglong2 sv = srow[mm];
                if (r == 0)  { nv.x = ONE2;  nv.y = ONE2;  }
                if (r == 99) { sv.x = ZERO2; sv.y = ZERO2; }

                // pair m = 2mm
                {
                    int m = 2 * mm;
                    ull Snext = shift_pair(P[m], P[m + 1]);          // S_{m+1}
                    ull t = mul2(cE[m], Snext);
                    t = fma2(cW[m], Scur, t);
                    t = fma2(cS[m], sv.x, t);
                    P[m] = fma2(cN[m], nv.x, t);
                    Scur = Snext;
                }
                // pair m = 2mm+1
                {
                    int m = 2 * mm + 1;
                    ull Snext = (m == 9) ? pack2(hi2(P[9]), rightb)
                                         : shift_pair(P[m], P[m + 1]);
                    ull t = mul2(cE[m], Snext);
                    t = fma2(cW[m], Scur, t);
                    t = fma2(cS[m], sv.y, t);
                    P[m] = fma2(cN[m], nv.y, t);
                    Scur = Snext;
                }
                ulonglong2 ov; ov.x = P[2 * mm]; ov.y = P[2 * mm + 1];
                orow[mm] = ov;
            }
        }
        __syncthreads();
        float* t = cur; cur = nxt; nxt = t;
    }

    // kappa = 2 * sum_c k[0,c] * (1 - T[0,c])
    if (act && r == 0) {
        float p = 0.0f;
#pragma unroll
        for (int m = 0; m < 10; m++) {
            p += k[c0 + 2*m]     * (1.0f - lo2(P[m]));
            p += k[c0 + 2*m + 1] * (1.0f - hi2(P[m]));
        }
        partial[s] = p;
    }
    __syncthreads();
    if (tid == 0)
        kappa[b] = 2.0f * (partial[0] + partial[1] + partial[2] + partial[3] + partial[4]);
}

// --------------------------- launcher ------------------------------
extern "C" void kernel_launch(void* const* d_in, const int* in_sizes, int n_in,
                              void* d_out, int out_size) {
    const float* pores = (const float*)d_in[0];
    const float* W1 = (const float*)d_in[1];
    const float* b1 = (const float*)d_in[2];
    const float* W2 = (const float*)d_in[3];
    const float* b2 = (const float*)d_in[4];
    const float* W3 = (const float*)d_in[5];
    const float* b3 = (const float*)d_in[6];
    const float* W4 = (const float*)d_in[7];
    const float* b4 = (const float*)d_in[8];

    float* out   = (float*)d_out;
    float* kappa = out;          // [32]
    float* cond  = out + B_SZ;   // [32,100,100]

    const int SMEM_JAC = (2 * 10000 + 8) * sizeof(float);  // ~80 KB
    cudaFuncSetAttribute(jacobi_kernel, cudaFuncAttributeMaxDynamicSharedMemorySize, SMEM_JAC);

    fc1_kernel<<<(B_SZ * 128 + 255) / 256, 256>>>(pores, W1, b1);
    fc2_kernel<<<(B_SZ * 256 + 255) / 256, 256>>>(W2, b2);
    fc3_kernel<<<(B_SZ * 512 + 255) / 256, 256>>>(W3, b3);
    dim3 g4((10000 + 127) / 128, KSPLIT);
    fc4_partial_kernel<<<g4, 128>>>(W4);
    dim3 g5((10000 + 127) / 128, B_SZ / 4);
    fc4_final_kernel<<<g5, 128>>>(b4, pores, cond);
    jacobi_kernel<<<B_SZ, 512, SMEM_JAC>>>(cond, kappa);
}